// round 11
// baseline (speedup 1.0000x reference)
#include <cuda_runtime.h>
#include <cstdint>
#include <math.h>

#define CDIM   1024
#define NHEADS 8
#define KD     128
#define BATCH  2
#define HH     48
#define WW     48
#define NTOK   (HH*WW)        // 2304
#define MTOT   (BATCH*NTOK)   // 4608

// ---------------- scratch (static device memory; no allocations) -------------
__device__ float g_q[MTOT*CDIM];
__device__ float g_k[MTOT*CDIM];
__device__ float g_v[MTOT*CDIM];
__device__ float g_vt[BATCH*NHEADS*KD*NTOK];     // tf32-rounded V, [b][h][d][tok]
__device__ float g_lepe[MTOT*CDIM];
__device__ float g_attn[BATCH*NHEADS*NTOK*KD];   // also: rounded x before attn
__device__ float g_wr[4*CDIM*CDIM];              // tf32-rounded weights

// ====================== common PTX helpers ==================================
__device__ __forceinline__ uint32_t smem_u32(const void* p) {
    uint32_t a;
    asm("{ .reg .u64 t; cvta.to.shared.u64 t, %1; cvt.u32.u64 %0, t; }"
        : "=r"(a) : "l"(p));
    return a;
}
__device__ __forceinline__ void cp16(uint32_t s, const void* g) {
    asm volatile("cp.async.cg.shared.global [%0], [%1], 16;" :: "r"(s), "l"(g));
}
__device__ __forceinline__ uint32_t f2tf32(float f) {
    uint32_t r; asm("cvt.rna.tf32.f32 %0, %1;" : "=r"(r) : "f"(f)); return r;
}
__device__ __forceinline__ float roundtf(float f) {
    return __uint_as_float(f2tf32(f));
}
__device__ __forceinline__ void mma_tf32(float* d, const uint32_t* a,
                                         uint32_t b0, uint32_t b1) {
    asm volatile(
      "mma.sync.aligned.m16n8k8.row.col.f32.tf32.tf32.f32 "
      "{%0,%1,%2,%3}, {%4,%5,%6,%7}, {%8,%9}, {%0,%1,%2,%3};"
      : "+f"(d[0]), "+f"(d[1]), "+f"(d[2]), "+f"(d[3])
      : "r"(a[0]), "r"(a[1]), "r"(a[2]), "r"(a[3]), "r"(b0), "r"(b1));
}
__device__ __forceinline__ void ldsm4(uint32_t* r, uint32_t addr) {
    asm volatile("ldmatrix.sync.aligned.m8n8.x4.shared.b16 {%0,%1,%2,%3}, [%4];"
        : "=r"(r[0]), "=r"(r[1]), "=r"(r[2]), "=r"(r[3]) : "r"(addr));
}

// ---------------- pre-round: fp32 -> tf32-in-fp32 ----------------------------
__global__ void round_x(const float* __restrict__ in, float* __restrict__ outp, int n)
{
    int i = blockIdx.x * blockDim.x + threadIdx.x;
    if (i < n) outp[i] = roundtf(in[i]);
}
__global__ void round_w(const float* __restrict__ w0, const float* __restrict__ w1,
                        const float* __restrict__ w2, const float* __restrict__ w3)
{
    int i = blockIdx.x * blockDim.x + threadIdx.x;
    if (i >= CDIM*CDIM) return;
    g_wr[i]               = roundtf(w0[i]);
    g_wr[i +   CDIM*CDIM] = roundtf(w1[i]);
    g_wr[i + 2*CDIM*CDIM] = roundtf(w2[i]);
    g_wr[i + 3*CDIM*CDIM] = roundtf(w3[i]);
}

// ====================== tf32 GEMM: 512 thr, 128x256 tile, 4-stage ===========
#define TKC 32
#define SSTR 36
#define AW (128*SSTR)           // 4608 words
#define BW (256*SSTR)           // 9216 words
#define STW_G (AW + BW)         // 13824 words per stage
#define NSTAGE 4
#define GEMM_SMEM (NSTAGE*STW_G*4)   // 221,184 B
#define NCHUNK_G (CDIM/TKC)          // 32

__device__ __forceinline__ void gemm_prefetch(
        uint32_t smb, int stage, const float* Ag, const float* Bg, int kc, int tid)
{
    uint32_t ab = smb + (uint32_t)(stage * STW_G) * 4;
    uint32_t bb = ab + AW * 4;
#pragma unroll
    for (int i = 0; i < 2; i++) {
        int idx = tid + i * 512;           // 0..1023 -> A 128x32
        int row = idx >> 3, c4 = (idx & 7) * 4;
        cp16(ab + (uint32_t)(row*SSTR + c4)*4, Ag + (size_t)row*CDIM + kc*TKC + c4);
    }
#pragma unroll
    for (int i = 0; i < 4; i++) {
        int idx = tid + i * 512;           // 0..2047 -> B 256x32
        int row = idx >> 3, c4 = (idx & 7) * 4;
        cp16(bb + (uint32_t)(row*SSTR + c4)*4, Bg + (size_t)row*CDIM + kc*TKC + c4);
    }
    asm volatile("cp.async.commit_group;");
}

// mode: 0 = q (rope, round), 1 = k (scale, rope, round), 2 = v plain, 3 = plain
__device__ __forceinline__ void gemm_body(
        const float* Ag, const float* Bg, const float* bias, float scale,
        float* out, int bm, int bn, int mode,
        const float* sin_t, const float* cos_t)
{
    extern __shared__ float sm[];
    const int tid = threadIdx.x;
    const int wid = tid >> 5, lane = tid & 31;
    const int gid = lane >> 2, tig = lane & 3;
    const int l15 = lane & 15, lhi = (lane >> 4) & 1;
    const int wm = wid & 1, wn = wid >> 1;          // 2 x 8 warp grid

    float acc[4][4][4];
#pragma unroll
    for (int i = 0; i < 4; i++)
#pragma unroll
        for (int j = 0; j < 4; j++)
#pragma unroll
            for (int r = 0; r < 4; r++) acc[i][j][r] = 0.f;

    const uint32_t smb = smem_u32(sm);
    uint32_t aoff[4], boff[2];
#pragma unroll
    for (int mt = 0; mt < 4; mt++)
        aoff[mt] = (uint32_t)((wm*64 + mt*16 + l15)*SSTR + lhi*4) * 4;
#pragma unroll
    for (int ntp = 0; ntp < 2; ntp++)
        boff[ntp] = (uint32_t)(AW + (wn*32 + ntp*16 + l15)*SSTR + lhi*4) * 4;

    gemm_prefetch(smb, 0, Ag, Bg, 0, tid);
    gemm_prefetch(smb, 1, Ag, Bg, 1, tid);
    gemm_prefetch(smb, 2, Ag, Bg, 2, tid);

    for (int kc = 0; kc < NCHUNK_G; kc++) {
        if (kc + 2 < NCHUNK_G)
            asm volatile("cp.async.wait_group 2;" ::: "memory");
        else if (kc + 1 < NCHUNK_G)
            asm volatile("cp.async.wait_group 1;" ::: "memory");
        else
            asm volatile("cp.async.wait_group 0;" ::: "memory");
        __syncthreads();
        if (kc + 3 < NCHUNK_G)
            gemm_prefetch(smb, (kc + 3) % NSTAGE, Ag, Bg, kc + 3, tid);

        const uint32_t ab = smb + (uint32_t)((kc % NSTAGE) * STW_G) * 4;

#pragma unroll
        for (int k8 = 0; k8 < TKC / 8; k8++) {
            uint32_t af[4][4], bv[2][4];
#pragma unroll
            for (int mt = 0; mt < 4; mt++)
                ldsm4(af[mt], ab + aoff[mt] + k8*32);
#pragma unroll
            for (int ntp = 0; ntp < 2; ntp++)
                ldsm4(bv[ntp], ab + boff[ntp] + k8*32);
#pragma unroll
            for (int mt = 0; mt < 4; mt++)
#pragma unroll
                for (int ntp = 0; ntp < 2; ntp++) {
                    mma_tf32(acc[mt][2*ntp],   af[mt], bv[ntp][0], bv[ntp][2]);
                    mma_tf32(acc[mt][2*ntp+1], af[mt], bv[ntp][1], bv[ntp][3]);
                }
        }
    }

#pragma unroll
    for (int mt = 0; mt < 4; mt++) {
        int r0 = bm + wm*64 + mt*16 + gid;
#pragma unroll
        for (int nt = 0; nt < 4; nt++) {
            int c = bn + wn*32 + nt*8 + tig*2;
            float2 bb = *(const float2*)&bias[c];
            float2 o0, o1;
            o0.x = (acc[mt][nt][0] + bb.x) * scale;
            o0.y = (acc[mt][nt][1] + bb.y) * scale;
            o1.x = (acc[mt][nt][2] + bb.x) * scale;
            o1.y = (acc[mt][nt][3] + bb.y) * scale;
            if (mode <= 1) {        // rope + tf32 round
                int d0 = c & 127;
                int n0 = r0 - ((r0 >= NTOK) ? NTOK : 0);
                int n1 = (r0+8) - ((r0+8 >= NTOK) ? NTOK : 0);
                float2 s0 = *(const float2*)&sin_t[n0*KD + d0];
                float2 c0_ = *(const float2*)&cos_t[n0*KD + d0];
                float2 s1 = *(const float2*)&sin_t[n1*KD + d0];
                float2 c1_ = *(const float2*)&cos_t[n1*KD + d0];
                float2 r0v, r1v;
                r0v.x = roundtf(o0.x*c0_.x + o0.y*s0.x);
                r0v.y = roundtf(o0.y*c0_.y - o0.x*s0.y);
                r1v.x = roundtf(o1.x*c1_.x + o1.y*s1.x);
                r1v.y = roundtf(o1.y*c1_.y - o1.x*s1.y);
                o0 = r0v; o1 = r1v;
            }
            *(float2*)&out[(size_t)r0 * CDIM + c]       = o0;
            *(float2*)&out[(size_t)(r0+8) * CDIM + c]   = o1;
        }
    }
}

__global__ __launch_bounds__(512,1) void gemm_qkv(
        const float* __restrict__ bq, const float* __restrict__ bk,
        const float* __restrict__ bv_, float scaling,
        const float* __restrict__ sin_t, const float* __restrict__ cos_t)
{
    int bx = blockIdx.x;                  // 0..11
    int sel = bx >> 2;
    int bn = (bx & 3) * 256;
    int bm = blockIdx.y * 128;
    const float* Ag = g_attn + (size_t)bm * CDIM;
    const float* Bg = g_wr + (size_t)sel * CDIM * CDIM + (size_t)bn * CDIM;
    const float* bias = (sel == 0) ? bq : (sel == 1) ? bk : bv_;
    float scale = (sel == 1) ? scaling : 1.f;
    float* out = (sel == 0) ? g_q : (sel == 1) ? g_k : g_v;
    gemm_body(Ag, Bg, bias, scale, out, bm, bn, sel, sin_t, cos_t);
}

__global__ __launch_bounds__(512,1) void gemm_out(
        const float* __restrict__ bo, float* __restrict__ outp)
{
    int bn = blockIdx.x * 256;
    int bm = blockIdx.y * 128;
    gemm_body(g_q + (size_t)bm * CDIM,
              g_wr + (size_t)3 * CDIM * CDIM + (size_t)bn * CDIM,
              bo, 1.f, outp, bm, bn, 3, nullptr, nullptr);
}

// ---------------- fuse: A for final GEMM (rounded) into g_q ------------------
__global__ void fuse_add(void)
{
    int i = blockIdx.x * blockDim.x + threadIdx.x;
    if (i >= MTOT * CDIM) return;
    int m = i >> 10, k = i & 1023;
    int b = m / NTOK, n = m - b * NTOK;
    int h = k >> 7,  d = k & 127;
    g_q[i] = roundtf(g_attn[((((size_t)b * NHEADS) + h) * NTOK + n) * KD + d]
                     + g_lepe[i]);
}

// ---------------- LePE: 5x5 depthwise conv on v ------------------------------
__global__ void lepe_conv(const float* __restrict__ wgt,
                          const float* __restrict__ bias)
{
    int idx = blockIdx.x * blockDim.x + threadIdx.x;
    if (idx >= MTOT * CDIM) return;
    int c = idx & (CDIM-1);
    int t = idx >> 10;
    int x = t % WW; t /= WW;
    int y = t % HH;
    int b = t / HH;
    float sum = bias[c];
#pragma unroll
    for (int ky = 0; ky < 5; ky++) {
        int yy = y + ky - 2;
        if (yy < 0 || yy >= HH) continue;
#pragma unroll
        for (int kx = 0; kx < 5; kx++) {
            int xx = x + kx - 2;
            if (xx < 0 || xx >= WW) continue;
            sum += g_v[(((size_t)(b*HH) + yy)*WW + xx)*CDIM + c]
                 * wgt[(ky*5 + kx)*CDIM + c];
        }
    }
    g_lepe[idx] = sum;
}

// ---------------- V transpose: g_v -> g_vt[b][h][d][tok], tf32-rounded -------
__global__ void transpose_v(void)
{
    __shared__ float t[32][33];
    int tid = threadIdx.x;
    int tx = tid & 31, ty = tid >> 5;
    int tok0 = blockIdx.x * 32, d0 = blockIdx.y * 32, bh = blockIdx.z;
    int b = bh >> 3, h = bh & 7;
    const float* src = g_v + (size_t)(b*NTOK)*CDIM + h*KD;
#pragma unroll
    for (int it = 0; it < 4; it++) {
        int tok = ty + it*8;
        t[tok][tx] = roundtf(src[(size_t)(tok0+tok)*CDIM + d0 + tx]);
    }
    __syncthreads();
    float* dst = g_vt + ((size_t)bh*KD + d0)*NTOK + tok0;
#pragma unroll
    for (int it = 0; it < 4; it++) {
        int d = ty + it*8;
        dst[(size_t)d*NTOK + tx] = t[tx][d];
    }
}

// ---------------- attention: tf32 mma + ldmatrix, double-buffered ------------
#define AM 128
#define AN 64
#define KST 132
#define VST 68
#define PST 68
#define QST 132
#define KW (AN*KST)          // 8448
#define VW (KD*VST)          // 8704
#define PSOFF (2*KW + 2*VW)  // 34304
#define ATTN_SMEM ((PSOFF + AM*PST) * 4)   // 172,032 B

__device__ __forceinline__ void attn_prefetch(
        uint32_t smb, int buf, const float* kg, const float* vt, int tid)
{
    uint32_t kb = smb + (uint32_t)(buf * KW) * 4;
    uint32_t vb = smb + (uint32_t)(2*KW + buf * VW) * 4;
#pragma unroll
    for (int i = 0; i < 8; i++) {
        int idx = tid + i * 256;          // 0..2047
        int r = idx >> 5, d4 = idx & 31;  // K: 64 rows x 32 float4
        cp16(kb + (uint32_t)(r*KST + d4*4)*4, kg + (size_t)r*CDIM + d4*4);
        int d = idx >> 4, c4 = idx & 15;  // V: 128 rows x 16 float4
        cp16(vb + (uint32_t)(d*VST + c4*4)*4, vt + (size_t)d*NTOK + c4*4);
    }
    asm volatile("cp.async.commit_group;");
}

__global__ __launch_bounds__(256,1) void attn_kernel(const float* __restrict__ mask)
{
    extern __shared__ float sm[];
    float* Ps = sm + PSOFF;

    const int tid = threadIdx.x;
    const int wid = tid >> 5, lane = tid & 31;
    const int gid = lane >> 2, tig = lane & 3;
    const int l15 = lane & 15, lhi = (lane >> 4) & 1;
    const int qt = blockIdx.x;
    const int bh = blockIdx.y;
    const int b = bh & 1, h = bh >> 1;    // adjacent y = same h -> mask L2 reuse
    const int qbase = qt * AM;
    const int wq0 = wid * 16;

    {   // stage Q through smem, hoist fragments
        const float* qg = g_q + (size_t)(b*NTOK + qbase)*CDIM + h*KD;
#pragma unroll
        for (int i = 0; i < 16; i++) {
            int idx = tid + i*256;
            int r = idx >> 5, d4 = idx & 31;
            *(float4*)&sm[r*QST + d4*4] = *(const float4*)(qg + (size_t)r*CDIM + d4*4);
        }
    }
    __syncthreads();
    uint32_t qf[16][4];
#pragma unroll
    for (int k8 = 0; k8 < 16; k8++) {
        const float* ap = sm + (wq0 + gid)*QST + k8*8 + tig;
        qf[k8][0] = __float_as_uint(ap[0]);
        qf[k8][1] = __float_as_uint(ap[8*QST]);
        qf[k8][2] = __float_as_uint(ap[4]);
        qf[k8][3] = __float_as_uint(ap[8*QST + 4]);
    }
    __syncthreads();

    const uint32_t smb = smem_u32(sm);
    uint32_t koff[4], voff[8], poff;
#pragma unroll
    for (int ntp = 0; ntp < 4; ntp++)
        koff[ntp] = (uint32_t)((ntp*16 + l15)*KST + lhi*4) * 4;
#pragma unroll
    for (int ntp = 0; ntp < 8; ntp++)
        voff[ntp] = (uint32_t)((ntp*16 + l15)*VST + lhi*4) * 4;
    poff = (uint32_t)(PSOFF + (wq0 + l15)*PST + lhi*4) * 4;

    const float* kg0 = g_k + (size_t)(b*NTOK)*CDIM + h*KD;
    const float* vt0 = g_vt + (size_t)(b*NHEADS + h) * KD * NTOK;
    attn_prefetch(smb, 0, kg0, vt0, tid);

    float rmax[2], rsum[2];
    float o[16][4];
#pragma unroll
    for (int r = 0; r < 2; r++) { rmax[r] = -1e30f; rsum[r] = 0.f; }
#pragma unroll
    for (int nt = 0; nt < 16; nt++)
#pragma unroll
        for (int r = 0; r < 4; r++) o[nt][r] = 0.f;

    const float* mrow0 = mask + ((size_t)h*NTOK + (qbase + wq0 + gid))*NTOK;
    const float* mrow1 = mrow0 + (size_t)8*NTOK;

    for (int kc = 0; kc < NTOK/AN; kc++) {
        const int kbase = kc * AN;
        const int buf = kc & 1;
        asm volatile("cp.async.wait_group 0;" ::: "memory");
        __syncthreads();
        if (kc + 1 < NTOK/AN)
            attn_prefetch(smb, buf ^ 1,
                          kg0 + (size_t)(kbase + AN)*CDIM,
                          vt0 + (kbase + AN), tid);

        const uint32_t ksb = smb + (uint32_t)(buf * KW) * 4;
        const uint32_t vsb = smb + (uint32_t)(2*KW + buf * VW) * 4;

        // ---- S = Q K^T ----
        float s[8][4];
#pragma unroll
        for (int nt = 0; nt < 8; nt++)
#pragma unroll
            for (int r = 0; r < 4; r++) s[nt][r] = 0.f;

#pragma unroll
        for (int k8 = 0; k8 < 16; k8++) {
#pragma unroll
            for (int ntp = 0; ntp < 4; ntp++) {
                uint32_t kv[4];
                ldsm4(kv, ksb + koff[ntp] + k8*32);
                mma_tf32(s[2*ntp],   qf[k8], kv[0], kv[2]);
                mma_tf32(s[2*ntp+1], qf[k8], kv[1], kv[3]);
            }
        }

        // ---- mask add ----
#pragma unroll
        for (int nt = 0; nt < 8; nt++) {
            int c = kbase + nt*8 + tig*2;
            float2 m0 = *(const float2*)(mrow0 + c);
            float2 m1 = *(const float2*)(mrow1 + c);
            s[nt][0] += m0.x; s[nt][1] += m0.y;
            s[nt][2] += m1.x; s[nt][3] += m1.y;
        }

        // ---- online softmax ----
#pragma unroll
        for (int r = 0; r < 2; r++) {
            float mx = -1e30f;
#pragma unroll
            for (int nt = 0; nt < 8; nt++)
                mx = fmaxf(mx, fmaxf(s[nt][2*r], s[nt][2*r+1]));
            mx = fmaxf(mx, __shfl_xor_sync(0xFFFFFFFFu, mx, 1, 4));
            mx = fmaxf(mx, __shfl_xor_sync(0xFFFFFFFFu, mx, 2, 4));
            float nm = fmaxf(rmax[r], mx);
            float corr = __expf(rmax[r] - nm);
            rmax[r] = nm;
            float ps = 0.f;
#pragma unroll
            for (int nt = 0; nt < 8; nt++) {
                float p0 = __expf(s[nt][2*r]   - nm);
                float p1 = __expf(s[nt][2*r+1] - nm);
                s[nt][2*r] = p0; s[nt][2*r+1] = p1;
                ps += p0 + p1;
            }
            ps += __shfl_xor_sync(0xFFFFFFFFu, ps, 1, 4);
            ps += __shfl_xor_sync(0xFFFFFFFFu, ps, 2, 4);
            rsum[r] = rsum[r]*corr + ps;
#pragma unroll
            for (int nt = 0; nt < 16; nt++) {
                o[nt][2*r]   *= corr;
                o[nt][2*r+1] *= corr;
            }
        }

        // ---- P -> smem, rounded to tf32 ----
#pragma unroll
        for (int nt = 0; nt < 8; nt++) {
            int c = nt*8 + tig*2;
            *(float2*)&Ps[(wq0 + gid)*PST + c] =
                make_float2(roundtf(s[nt][0]), roundtf(s[nt][1]));
            *(float2*)&Ps[(wq0 + gid + 8)*PST + c] =
                make_float2(roundtf(s[nt][2]), roundtf(s[nt][3]));
        }
        __syncwarp();

        // ---- O += P V ----
#pragma unroll
        for (int k8 = 0; k8 < 8; k8++) {
            uint32_t pf[4];
            ldsm4(pf, smb + poff + k8*32);
#pragma unroll
            for (int ntp = 0; ntp < 8; ntp++) {
                uint32_t vv[4];
                ldsm4(vv, vsb + voff[ntp] + k8*32);
                mma_tf32(o[2*ntp],   pf, vv[0], vv[2]);
                mma_tf32(o[2*ntp+1], pf, vv[1], vv[3]);
            }
        }
        __syncwarp();
    }

    // ---- epilogue ----
    float* og = g_attn + (((size_t)(b*NHEADS) + h)*NTOK + qbase + wq0)*KD;
#pragma unroll
    for (int r = 0; r < 2; r++) {
        float inv = 1.f / rsum[r];
        float* orow = og + (size_t)(gid + 8*r)*KD;
#pragma unroll
        for (int nt = 0; nt < 16; nt++) {
            float2 w;
            w.x = o[nt][2*r]   * inv;
            w.y = o[nt][2*r+1] * inv;
            *(float2*)&orow[nt*8 + tig*2] = w;
        }
    }
}

// ---------------- launcher ---------------------------------------------------
extern "C" void kernel_launch(void* const* d_in, const int* in_sizes, int n_in,
                              void* d_out, int out_size)
{
    const float* x      = (const float*)d_in[0];
    const float* sin_t  = (const float*)d_in[1];
    const float* cos_t  = (const float*)d_in[2];
    const float* mask   = (const float*)d_in[3];
    const float* Wq     = (const float*)d_in[4];
    const float* bq     = (const float*)d_in[5];
    const float* Wk     = (const float*)d_in[6];
    const float* bk     = (const float*)d_in[7];
    const float* Wv     = (const float*)d_in[8];
    const float* bv     = (const float*)d_in[9];
    const float* lepe_w = (const float*)d_in[10];
    const float* lepe_b = (const float*)d_in[11];
    const float* Wo     = (const float*)d_in[12];
    const float* bo     = (const float*)d_in[13];
    float* out = (float*)d_out;

    const float scaling = 0.08838834764831845f;   // 1/sqrt(128)

    const int nx = MTOT * CDIM;
    float* g_attn_p;  cudaGetSymbolAddress((void**)&g_attn_p, g_attn);
    round_x<<<(nx + 511)/512, 512>>>(x, g_attn_p, nx);
    round_w<<<(CDIM*CDIM + 511)/512, 512>>>(Wq, Wk, Wv, Wo);

    cudaFuncSetAttribute(gemm_qkv,
                         cudaFuncAttributeMaxDynamicSharedMemorySize, GEMM_SMEM);
    cudaFuncSetAttribute(gemm_out,
                         cudaFuncAttributeMaxDynamicSharedMemorySize, GEMM_SMEM);

    gemm_qkv<<<dim3(12, MTOT/128), 512, GEMM_SMEM>>>(bq, bk, bv, scaling,
                                                     sin_t, cos_t);

    lepe_conv<<<(nx + 255)/256, 256>>>(lepe_w, lepe_b);
    transpose_v<<<dim3(NTOK/32, KD/32, BATCH*NHEADS), 256>>>();

    cudaFuncSetAttribute(attn_kernel,
                         cudaFuncAttributeMaxDynamicSharedMemorySize, ATTN_SMEM);
    attn_kernel<<<dim3(NTOK/AM, BATCH*NHEADS), 256, ATTN_SMEM>>>(mask);

    fuse_add<<<(nx + 255)/256, 256>>>();
    gemm_out<<<dim3(4, MTOT/128), 512, GEMM_SMEM>>>(bo, out);
}

// round 14
// speedup vs baseline: 1.0618x; 1.0618x over previous
#include <cuda_runtime.h>
#include <cstdint>
#include <math.h>

#define CDIM   1024
#define NHEADS 8
#define KD     128
#define BATCH  2
#define HH     48
#define WW     48
#define NTOK   (HH*WW)        // 2304
#define MTOT   (BATCH*NTOK)   // 4608

// ---------------- scratch (static device memory; no allocations) -------------
__device__ float g_q[MTOT*CDIM];
__device__ float g_k[MTOT*CDIM];
__device__ float g_v[MTOT*CDIM];
__device__ float g_vt[BATCH*NHEADS*KD*NTOK];     // tf32-rounded V, [b][h][d][tok]
__device__ float g_lepe[MTOT*CDIM];
__device__ float g_attn[BATCH*NHEADS*NTOK*KD];   // also: rounded x before attn
__device__ float g_wr[4*CDIM*CDIM];              // tf32-rounded weights

// ====================== common PTX helpers ==================================
__device__ __forceinline__ uint32_t smem_u32(const void* p) {
    uint32_t a;
    asm("{ .reg .u64 t; cvta.to.shared.u64 t, %1; cvt.u32.u64 %0, t; }"
        : "=r"(a) : "l"(p));
    return a;
}
__device__ __forceinline__ void cp16(uint32_t s, const void* g) {
    asm volatile("cp.async.cg.shared.global [%0], [%1], 16;" :: "r"(s), "l"(g));
}
__device__ __forceinline__ uint32_t f2tf32(float f) {
    uint32_t r; asm("cvt.rna.tf32.f32 %0, %1;" : "=r"(r) : "f"(f)); return r;
}
__device__ __forceinline__ float roundtf(float f) {
    return __uint_as_float(f2tf32(f));
}
__device__ __forceinline__ void mma_tf32(float* d, const uint32_t* a,
                                         uint32_t b0, uint32_t b1) {
    asm volatile(
      "mma.sync.aligned.m16n8k8.row.col.f32.tf32.tf32.f32 "
      "{%0,%1,%2,%3}, {%4,%5,%6,%7}, {%8,%9}, {%0,%1,%2,%3};"
      : "+f"(d[0]), "+f"(d[1]), "+f"(d[2]), "+f"(d[3])
      : "r"(a[0]), "r"(a[1]), "r"(a[2]), "r"(a[3]), "r"(b0), "r"(b1));
}
__device__ __forceinline__ void ldsm4(uint32_t* r, uint32_t addr) {
    asm volatile("ldmatrix.sync.aligned.m8n8.x4.shared.b16 {%0,%1,%2,%3}, [%4];"
        : "=r"(r[0]), "=r"(r[1]), "=r"(r[2]), "=r"(r[3]) : "r"(addr));
}

// ---------------- pre-round: fp32 -> tf32-in-fp32 (float4) -------------------
__device__ __forceinline__ float4 round4(float4 v) {
    v.x = roundtf(v.x); v.y = roundtf(v.y);
    v.z = roundtf(v.z); v.w = roundtf(v.w);
    return v;
}
__global__ void round_x(const float4* __restrict__ in, float4* __restrict__ outp, int n4)
{
    int i = blockIdx.x * blockDim.x + threadIdx.x;
    if (i < n4) outp[i] = round4(in[i]);
}
__global__ void round_w(const float4* __restrict__ w0, const float4* __restrict__ w1,
                        const float4* __restrict__ w2, const float4* __restrict__ w3)
{
    int i = blockIdx.x * blockDim.x + threadIdx.x;
    const int n4 = CDIM*CDIM/4;
    if (i >= n4) return;
    float4* wr = (float4*)g_wr;
    wr[i]        = round4(w0[i]);
    wr[i +   n4] = round4(w1[i]);
    wr[i + 2*n4] = round4(w2[i]);
    wr[i + 3*n4] = round4(w3[i]);
}

// ====================== tf32 GEMM: 512 thr, 128x256 tile, 4-stage ===========
#define TKC 32
#define SSTR 36
#define AW (128*SSTR)           // 4608 words
#define BW (256*SSTR)           // 9216 words
#define STW_G (AW + BW)         // 13824 words per stage
#define NSTAGE 4
#define GEMM_SMEM (NSTAGE*STW_G*4)   // 221,184 B
#define NCHUNK_G (CDIM/TKC)          // 32

__device__ __forceinline__ void gemm_prefetch(
        uint32_t smb, int stage, const float* Ag, const float* Bg, int kc, int tid)
{
    uint32_t ab = smb + (uint32_t)(stage * STW_G) * 4;
    uint32_t bb = ab + AW * 4;
#pragma unroll
    for (int i = 0; i < 2; i++) {
        int idx = tid + i * 512;           // 0..1023 -> A 128x32
        int row = idx >> 3, c4 = (idx & 7) * 4;
        cp16(ab + (uint32_t)(row*SSTR + c4)*4, Ag + (size_t)row*CDIM + kc*TKC + c4);
    }
#pragma unroll
    for (int i = 0; i < 4; i++) {
        int idx = tid + i * 512;           // 0..2047 -> B 256x32
        int row = idx >> 3, c4 = (idx & 7) * 4;
        cp16(bb + (uint32_t)(row*SSTR + c4)*4, Bg + (size_t)row*CDIM + kc*TKC + c4);
    }
    asm volatile("cp.async.commit_group;");
}

// mode: 0 = q (rope, round), 1 = k (scale, rope, round), 2 = v plain, 3 = plain
__device__ __forceinline__ void gemm_body(
        const float* Ag, const float* Bg, const float* bias, float scale,
        float* out, int bm, int bn, int mode,
        const float* sin_t, const float* cos_t)
{
    extern __shared__ float sm[];
    const int tid = threadIdx.x;
    const int wid = tid >> 5, lane = tid & 31;
    const int gid = lane >> 2, tig = lane & 3;
    const int l15 = lane & 15, lhi = (lane >> 4) & 1;
    const int wm = wid & 1, wn = wid >> 1;          // 2 x 8 warp grid

    float acc[4][4][4];
#pragma unroll
    for (int i = 0; i < 4; i++)
#pragma unroll
        for (int j = 0; j < 4; j++)
#pragma unroll
            for (int r = 0; r < 4; r++) acc[i][j][r] = 0.f;

    const uint32_t smb = smem_u32(sm);
    uint32_t aoff[4], boff[2];
#pragma unroll
    for (int mt = 0; mt < 4; mt++)
        aoff[mt] = (uint32_t)((wm*64 + mt*16 + l15)*SSTR + lhi*4) * 4;
#pragma unroll
    for (int ntp = 0; ntp < 2; ntp++)
        boff[ntp] = (uint32_t)(AW + (wn*32 + ntp*16 + l15)*SSTR + lhi*4) * 4;

    gemm_prefetch(smb, 0, Ag, Bg, 0, tid);
    gemm_prefetch(smb, 1, Ag, Bg, 1, tid);
    gemm_prefetch(smb, 2, Ag, Bg, 2, tid);

    for (int kc = 0; kc < NCHUNK_G; kc++) {
        if (kc + 2 < NCHUNK_G)
            asm volatile("cp.async.wait_group 2;" ::: "memory");
        else if (kc + 1 < NCHUNK_G)
            asm volatile("cp.async.wait_group 1;" ::: "memory");
        else
            asm volatile("cp.async.wait_group 0;" ::: "memory");
        __syncthreads();
        if (kc + 3 < NCHUNK_G)
            gemm_prefetch(smb, (kc + 3) % NSTAGE, Ag, Bg, kc + 3, tid);

        const uint32_t ab = smb + (uint32_t)((kc % NSTAGE) * STW_G) * 4;

#pragma unroll
        for (int k8 = 0; k8 < TKC / 8; k8++) {
            uint32_t af[4][4], bv[2][4];
#pragma unroll
            for (int mt = 0; mt < 4; mt++)
                ldsm4(af[mt], ab + aoff[mt] + k8*32);
#pragma unroll
            for (int ntp = 0; ntp < 2; ntp++)
                ldsm4(bv[ntp], ab + boff[ntp] + k8*32);
#pragma unroll
            for (int mt = 0; mt < 4; mt++)
#pragma unroll
                for (int ntp = 0; ntp < 2; ntp++) {
                    mma_tf32(acc[mt][2*ntp],   af[mt], bv[ntp][0], bv[ntp][2]);
                    mma_tf32(acc[mt][2*ntp+1], af[mt], bv[ntp][1], bv[ntp][3]);
                }
        }
    }

#pragma unroll
    for (int mt = 0; mt < 4; mt++) {
        int r0 = bm + wm*64 + mt*16 + gid;
#pragma unroll
        for (int nt = 0; nt < 4; nt++) {
            int c = bn + wn*32 + nt*8 + tig*2;
            float2 bb = *(const float2*)&bias[c];
            float2 o0, o1;
            o0.x = (acc[mt][nt][0] + bb.x) * scale;
            o0.y = (acc[mt][nt][1] + bb.y) * scale;
            o1.x = (acc[mt][nt][2] + bb.x) * scale;
            o1.y = (acc[mt][nt][3] + bb.y) * scale;
            if (mode <= 1) {        // rope + tf32 round
                int d0 = c & 127;
                int n0 = r0 - ((r0 >= NTOK) ? NTOK : 0);
                int n1 = (r0+8) - ((r0+8 >= NTOK) ? NTOK : 0);
                float2 s0 = *(const float2*)&sin_t[n0*KD + d0];
                float2 c0_ = *(const float2*)&cos_t[n0*KD + d0];
                float2 s1 = *(const float2*)&sin_t[n1*KD + d0];
                float2 c1_ = *(const float2*)&cos_t[n1*KD + d0];
                float2 r0v, r1v;
                r0v.x = roundtf(o0.x*c0_.x + o0.y*s0.x);
                r0v.y = roundtf(o0.y*c0_.y - o0.x*s0.y);
                r1v.x = roundtf(o1.x*c1_.x + o1.y*s1.x);
                r1v.y = roundtf(o1.y*c1_.y - o1.x*s1.y);
                o0 = r0v; o1 = r1v;
            }
            *(float2*)&out[(size_t)r0 * CDIM + c]       = o0;
            *(float2*)&out[(size_t)(r0+8) * CDIM + c]   = o1;
        }
    }
}

__global__ __launch_bounds__(512,1) void gemm_qkv(
        const float* __restrict__ bq, const float* __restrict__ bk,
        const float* __restrict__ bv_, float scaling,
        const float* __restrict__ sin_t, const float* __restrict__ cos_t)
{
    int bx = blockIdx.x;                  // 0..11
    int sel = bx >> 2;
    int bn = (bx & 3) * 256;
    int bm = blockIdx.y * 128;
    const float* Ag = g_attn + (size_t)bm * CDIM;
    const float* Bg = g_wr + (size_t)sel * CDIM * CDIM + (size_t)bn * CDIM;
    const float* bias = (sel == 0) ? bq : (sel == 1) ? bk : bv_;
    float scale = (sel == 1) ? scaling : 1.f;
    float* out = (sel == 0) ? g_q : (sel == 1) ? g_k : g_v;
    gemm_body(Ag, Bg, bias, scale, out, bm, bn, sel, sin_t, cos_t);
}

__global__ __launch_bounds__(512,1) void gemm_out(
        const float* __restrict__ bo, float* __restrict__ outp)
{
    int bn = blockIdx.x * 256;
    int bm = blockIdx.y * 128;
    gemm_body(g_q + (size_t)bm * CDIM,
              g_wr + (size_t)3 * CDIM * CDIM + (size_t)bn * CDIM,
              bo, 1.f, outp, bm, bn, 3, nullptr, nullptr);
}

// ---------------- fuse: A for final GEMM (rounded) into g_q, float4 ----------
__global__ void fuse_add(void)
{
    int i = blockIdx.x * blockDim.x + threadIdx.x;   // float4 index
    if (i >= MTOT * (CDIM/4)) return;
    int m = i >> 8, k4 = (i & 255) * 4;
    int b = (m >= NTOK) ? 1 : 0;
    int n = m - b * NTOK;
    int h = k4 >> 7, d = k4 & 127;
    float4 a = *(const float4*)&g_attn[((((size_t)b * NHEADS) + h) * NTOK + n) * KD + d];
    float4 l = *(const float4*)&g_lepe[(size_t)m * CDIM + k4];
    float4 r;
    r.x = roundtf(a.x + l.x); r.y = roundtf(a.y + l.y);
    r.z = roundtf(a.z + l.z); r.w = roundtf(a.w + l.w);
    *(float4*)&g_q[(size_t)m * CDIM + k4] = r;
}

// ---------------- LePE: 5x5 depthwise conv on v, float4 over channels --------
__global__ void lepe_conv(const float* __restrict__ wgt,
                          const float* __restrict__ bias)
{
    int idx = blockIdx.x * blockDim.x + threadIdx.x;  // float4 index
    if (idx >= MTOT * (CDIM/4)) return;
    int c4 = (idx & 255) * 4;
    int t = idx >> 8;
    int x = t % WW; t /= WW;
    int y = t % HH;
    int b = t / HH;
    float4 sum = *(const float4*)&bias[c4];
#pragma unroll
    for (int ky = 0; ky < 5; ky++) {
        int yy = y + ky - 2;
        if (yy < 0 || yy >= HH) continue;
#pragma unroll
        for (int kx = 0; kx < 5; kx++) {
            int xx = x + kx - 2;
            if (xx < 0 || xx >= WW) continue;
            float4 v = *(const float4*)&g_v[(((size_t)(b*HH) + yy)*WW + xx)*CDIM + c4];
            float4 w = *(const float4*)&wgt[(ky*5 + kx)*CDIM + c4];
            sum.x += v.x*w.x; sum.y += v.y*w.y;
            sum.z += v.z*w.z; sum.w += v.w*w.w;
        }
    }
    *(float4*)&g_lepe[((size_t)(b*HH + y)*WW + x)*CDIM + c4] = sum;
}

// ---------------- V transpose: g_v -> g_vt[b][h][d][tok], tf32-rounded -------
__global__ void transpose_v(void)
{
    __shared__ float t[32][33];
    int tid = threadIdx.x;
    int tx = tid & 31, ty = tid >> 5;
    int tok0 = blockIdx.x * 32, d0 = blockIdx.y * 32, bh = blockIdx.z;
    int b = bh >> 3, h = bh & 7;
    const float* src = g_v + (size_t)(b*NTOK)*CDIM + h*KD;
#pragma unroll
    for (int it = 0; it < 4; it++) {
        int tok = ty + it*8;
        t[tok][tx] = roundtf(src[(size_t)(tok0+tok)*CDIM + d0 + tx]);
    }
    __syncthreads();
    float* dst = g_vt + ((size_t)bh*KD + d0)*NTOK + tok0;
#pragma unroll
    for (int it = 0; it < 4; it++) {
        int d = ty + it*8;
        dst[(size_t)d*NTOK + tx] = t[tx][d];
    }
}

// ---------------- attention: tf32 mma + ldmatrix, double-buffered ------------
#define AM 128
#define AN 64
#define KST 132
#define VST 68
#define PST 68
#define QST 132
#define KW (AN*KST)          // 8448
#define VW (KD*VST)          // 8704
#define PSOFF (2*KW + 2*VW)  // 34304
#define ATTN_SMEM ((PSOFF + AM*PST) * 4)   // 172,032 B

__device__ __forceinline__ void attn_prefetch(
        uint32_t smb, int buf, const float* kg, const float* vt, int tid)
{
    uint32_t kb = smb + (uint32_t)(buf * KW) * 4;
    uint32_t vb = smb + (uint32_t)(2*KW + buf * VW) * 4;
#pragma unroll
    for (int i = 0; i < 8; i++) {
        int idx = tid + i * 256;          // 0..2047
        int r = idx >> 5, d4 = idx & 31;  // K: 64 rows x 32 float4
        cp16(kb + (uint32_t)(r*KST + d4*4)*4, kg + (size_t)r*CDIM + d4*4);
        int d = idx >> 4, c4 = idx & 15;  // V: 128 rows x 16 float4
        cp16(vb + (uint32_t)(d*VST + c4*4)*4, vt + (size_t)d*NTOK + c4*4);
    }
    asm volatile("cp.async.commit_group;");
}

__global__ __launch_bounds__(256,1) void attn_kernel(const float* __restrict__ mask)
{
    extern __shared__ float sm[];
    float* Ps = sm + PSOFF;

    const int tid = threadIdx.x;
    const int wid = tid >> 5, lane = tid & 31;
    const int gid = lane >> 2, tig = lane & 3;
    const int l15 = lane & 15, lhi = (lane >> 4) & 1;
    const int qt = blockIdx.x;
    const int bh = blockIdx.y;
    const int b = bh & 1, h = bh >> 1;    // adjacent y = same h -> mask L2 reuse
    const int qbase = qt * AM;
    const int wq0 = wid * 16;

    {   // stage Q through smem, hoist fragments
        const float* qg = g_q + (size_t)(b*NTOK + qbase)*CDIM + h*KD;
#pragma unroll
        for (int i = 0; i < 16; i++) {
            int idx = tid + i*256;
            int r = idx >> 5, d4 = idx & 31;
            *(float4*)&sm[r*QST + d4*4] = *(const float4*)(qg + (size_t)r*CDIM + d4*4);
        }
    }
    __syncthreads();
    uint32_t qf[16][4];
#pragma unroll
    for (int k8 = 0; k8 < 16; k8++) {
        const float* ap = sm + (wq0 + gid)*QST + k8*8 + tig;
        qf[k8][0] = __float_as_uint(ap[0]);
        qf[k8][1] = __float_as_uint(ap[8*QST]);
        qf[k8][2] = __float_as_uint(ap[4]);
        qf[k8][3] = __float_as_uint(ap[8*QST + 4]);
    }
    __syncthreads();

    const uint32_t smb = smem_u32(sm);
    uint32_t koff[4], voff[8], poff;
#pragma unroll
    for (int ntp = 0; ntp < 4; ntp++)
        koff[ntp] = (uint32_t)((ntp*16 + l15)*KST + lhi*4) * 4;
#pragma unroll
    for (int ntp = 0; ntp < 8; ntp++)
        voff[ntp] = (uint32_t)((ntp*16 + l15)*VST + lhi*4) * 4;
    poff = (uint32_t)(PSOFF + (wq0 + l15)*PST + lhi*4) * 4;

    const float* kg0 = g_k + (size_t)(b*NTOK)*CDIM + h*KD;
    const float* vt0 = g_vt + (size_t)(b*NHEADS + h) * KD * NTOK;
    attn_prefetch(smb, 0, kg0, vt0, tid);

    float rmax[2], rsum[2];
    float o[16][4];
#pragma unroll
    for (int r = 0; r < 2; r++) { rmax[r] = -1e30f; rsum[r] = 0.f; }
#pragma unroll
    for (int nt = 0; nt < 16; nt++)
#pragma unroll
        for (int r = 0; r < 4; r++) o[nt][r] = 0.f;

    const float* mrow0 = mask + ((size_t)h*NTOK + (qbase + wq0 + gid))*NTOK;
    const float* mrow1 = mrow0 + (size_t)8*NTOK;

    for (int kc = 0; kc < NTOK/AN; kc++) {
        const int kbase = kc * AN;
        const int buf = kc & 1;
        asm volatile("cp.async.wait_group 0;" ::: "memory");
        __syncthreads();
        if (kc + 1 < NTOK/AN)
            attn_prefetch(smb, buf ^ 1,
                          kg0 + (size_t)(kbase + AN)*CDIM,
                          vt0 + (kbase + AN), tid);

        const uint32_t ksb = smb + (uint32_t)(buf * KW) * 4;
        const uint32_t vsb = smb + (uint32_t)(2*KW + buf * VW) * 4;

        // ---- mask prefetch (hidden behind S MMAs) ----
        float2 mr0[8], mr1[8];
#pragma unroll
        for (int nt = 0; nt < 8; nt++) {
            int c = kbase + nt*8 + tig*2;
            mr0[nt] = *(const float2*)(mrow0 + c);
            mr1[nt] = *(const float2*)(mrow1 + c);
        }

        // ---- S = Q K^T ----
        float s[8][4];
#pragma unroll
        for (int nt = 0; nt < 8; nt++)
#pragma unroll
            for (int r = 0; r < 4; r++) s[nt][r] = 0.f;

#pragma unroll
        for (int k8 = 0; k8 < 16; k8++) {
#pragma unroll
            for (int ntp = 0; ntp < 4; ntp++) {
                uint32_t kv[4];
                ldsm4(kv, ksb + koff[ntp] + k8*32);
                mma_tf32(s[2*ntp],   qf[k8], kv[0], kv[2]);
                mma_tf32(s[2*ntp+1], qf[k8], kv[1], kv[3]);
            }
        }

        // ---- mask add ----
#pragma unroll
        for (int nt = 0; nt < 8; nt++) {
            s[nt][0] += mr0[nt].x; s[nt][1] += mr0[nt].y;
            s[nt][2] += mr1[nt].x; s[nt][3] += mr1[nt].y;
        }

        // ---- online softmax ----
        float corr[2];
#pragma unroll
        for (int r = 0; r < 2; r++) {
            float mx = -1e30f;
#pragma unroll
            for (int nt = 0; nt < 8; nt++)
                mx = fmaxf(mx, fmaxf(s[nt][2*r], s[nt][2*r+1]));
            mx = fmaxf(mx, __shfl_xor_sync(0xFFFFFFFFu, mx, 1, 4));
            mx = fmaxf(mx, __shfl_xor_sync(0xFFFFFFFFu, mx, 2, 4));
            float nm = fmaxf(rmax[r], mx);
            corr[r] = __expf(rmax[r] - nm);
            rmax[r] = nm;
            float ps = 0.f;
#pragma unroll
            for (int nt = 0; nt < 8; nt++) {
                float p0 = __expf(s[nt][2*r]   - nm);
                float p1 = __expf(s[nt][2*r+1] - nm);
                s[nt][2*r] = p0; s[nt][2*r+1] = p1;
                ps += p0 + p1;
            }
            ps += __shfl_xor_sync(0xFFFFFFFFu, ps, 1, 4);
            ps += __shfl_xor_sync(0xFFFFFFFFu, ps, 2, 4);
            rsum[r] = rsum[r]*corr[r] + ps;
        }
        // warp-voted O rescale (skip when max unchanged everywhere)
        if (!__all_sync(0xFFFFFFFFu, (corr[0] == 1.f) && (corr[1] == 1.f))) {
#pragma unroll
            for (int nt = 0; nt < 16; nt++) {
                o[nt][0] *= corr[0]; o[nt][1] *= corr[0];
                o[nt][2] *= corr[1]; o[nt][3] *= corr[1];
            }
        }

        // ---- P -> smem, rounded to tf32 ----
#pragma unroll
        for (int nt = 0; nt < 8; nt++) {
            int c = nt*8 + tig*2;
            *(float2*)&Ps[(wq0 + gid)*PST + c] =
                make_float2(roundtf(s[nt][0]), roundtf(s[nt][1]));
            *(float2*)&Ps[(wq0 + gid + 8)*PST + c] =
                make_float2(roundtf(s[nt][2]), roundtf(s[nt][3]));
        }
        __syncwarp();

        // ---- O += P V ----
#pragma unroll
        for (int k8 = 0; k8 < 8; k8++) {
            uint32_t pf[4];
            ldsm4(pf, smb + poff + k8*32);
#pragma unroll
            for (int ntp = 0; ntp < 8; ntp++) {
                uint32_t vv[4];
                ldsm4(vv, vsb + voff[ntp] + k8*32);
                mma_tf32(o[2*ntp],   pf, vv[0], vv[2]);
                mma_tf32(o[2*ntp+1], pf, vv[1], vv[3]);
            }
        }
        __syncwarp();
    }

    // ---- epilogue ----
    float* og = g_attn + (((size_t)(b*NHEADS) + h)*NTOK + qbase + wq0)*KD;
#pragma unroll
    for (int r = 0; r < 2; r++) {
        float inv = 1.f / rsum[r];
        float* orow = og + (size_t)(gid + 8*r)*KD;
#pragma unroll
        for (int nt = 0; nt < 16; nt++) {
            float2 w;
            w.x = o[nt][2*r]   * inv;
            w.y = o[nt][2*r+1] * inv;
            *(float2*)&orow[nt*8 + tig*2] = w;
        }
    }
}

// ---------------- launcher ---------------------------------------------------
extern "C" void kernel_launch(void* const* d_in, const int* in_sizes, int n_in,
                              void* d_out, int out_size)
{
    const float* x      = (const float*)d_in[0];
    const float* sin_t  = (const float*)d_in[1];
    const float* cos_t  = (const float*)d_in[2];
    const float* mask   = (const float*)d_in[3];
    const float* Wq     = (const float*)d_in[4];
    const float* bq     = (const float*)d_in[5];
    const float* Wk     = (const float*)d_in[6];
    const float* bk     = (const float*)d_in[7];
    const float* Wv     = (const float*)d_in[8];
    const float* bv     = (const float*)d_in[9];
    const float* lepe_w = (const float*)d_in[10];
    const float* lepe_b = (const float*)d_in[11];
    const float* Wo     = (const float*)d_in[12];
    const float* bo     = (const float*)d_in[13];
    float* out = (float*)d_out;

    const float scaling = 0.08838834764831845f;   // 1/sqrt(128)

    const int nx4 = MTOT * CDIM / 4;
    const int nw4 = CDIM * CDIM / 4;
    float* g_attn_p;  cudaGetSymbolAddress((void**)&g_attn_p, g_attn);
    round_x<<<(nx4 + 255)/256, 256>>>((const float4*)x, (float4*)g_attn_p, nx4);
    round_w<<<(nw4 + 255)/256, 256>>>((const float4*)Wq, (const float4*)Wk,
                                      (const float4*)Wv, (const float4*)Wo);

    cudaFuncSetAttribute(gemm_qkv,
                         cudaFuncAttributeMaxDynamicSharedMemorySize, GEMM_SMEM);
    cudaFuncSetAttribute(gemm_out,
                         cudaFuncAttributeMaxDynamicSharedMemorySize, GEMM_SMEM);

    gemm_qkv<<<dim3(12, MTOT/128), 512, GEMM_SMEM>>>(bq, bk, bv, scaling,
                                                     sin_t, cos_t);

    lepe_conv<<<(nx4 + 255)/256, 256>>>(lepe_w, lepe_b);
    transpose_v<<<dim3(NTOK/32, KD/32, BATCH*NHEADS), 256>>>();

    cudaFuncSetAttribute(attn_kernel,
                         cudaFuncAttributeMaxDynamicSharedMemorySize, ATTN_SMEM);
    attn_kernel<<<dim3(NTOK/AM, BATCH*NHEADS), 256, ATTN_SMEM>>>(mask);

    fuse_add<<<(nx4 + 255)/256, 256>>>();
    gemm_out<<<dim3(4, MTOT/128), 512, GEMM_SMEM>>>(bo, out);
}